// round 3
// baseline (speedup 1.0000x reference)
#include <cuda_runtime.h>

// Problem constants: B=64, D=2048, UNITS=1024, NW=64
#define Bsz    64
#define Dd     2048
#define UNITSn 1024
#define NWn    64

#define UPC  8                 // units per CTA
#define NCTA (UNITSn / UPC)    // 128 CTAs
#define BKt  128               // k-tile width
#define NT   (Dd / BKt)        // 16 tiles
#define XST  132               // xs row stride (floats): 16B-aligned, conflict-free LDS.128

__device__ __forceinline__ void fma2(unsigned long long& d,
                                     unsigned long long a,
                                     unsigned long long b) {
    asm("fma.rn.f32x2 %0, %1, %2, %0;" : "+l"(d) : "l"(a), "l"(b));
}
__device__ __forceinline__ void cp16(unsigned s, const void* g) {
    asm volatile("cp.async.cg.shared.global [%0], [%1], 16;" :: "r"(s), "l"(g));
}
__device__ __forceinline__ void cp_commit() {
    asm volatile("cp.async.commit_group;");
}
template <int N> __device__ __forceinline__ void cp_wait() {
    asm volatile("cp.async.wait_group %0;" :: "n"(N));
}

// Prefetch x tile t (64 x 128 fp32 = 32KB) into xs buffer via cp.async.
__device__ __forceinline__ void load_x_tile(const float* __restrict__ x,
                                            unsigned xs_buf_u32, int t, int tid) {
    const int k0 = t * BKt;
    #pragma unroll
    for (int i = 0; i < 8; i++) {
        int idx = i * 256 + tid;          // 0..2047 float4 slots
        int r   = idx >> 5;               // batch row 0..63
        int c   = (idx & 31) << 2;        // k offset 0,4,...,124
        cp16(xs_buf_u32 + (unsigned)((r * XST + c) * 4),
             x + (long)r * Dd + k0 + c);
    }
    cp_commit();
}

// ---------------------------------------------------------------------------
// Fully fused: build W rows in smem from hashed indices, then GEMM vs x with
// a 2-stage cp.async pipeline. out[b, u0+j] = sum_k x[b,k]*W[u0+j,k] + bias.
// Thread (b = tid&63, z = tid>>6) owns k-segment z of all 8 units; cross-z
// reduction in smem at the end. No device scratch, no atomics, one launch.
// ---------------------------------------------------------------------------
__global__ __launch_bounds__(256, 1) void fused_kernel(const float* __restrict__ x,
                                                       const float* __restrict__ w,
                                                       const float* __restrict__ bias,
                                                       const int* __restrict__ indices,
                                                       float* __restrict__ out,
                                                       int L, unsigned magicL) {
    extern __shared__ float sm[];
    float* ws  = sm;                       // [UPC][Dd]      64 KB (reused as reduce buf)
    float* xs  = sm + UPC * Dd;            // [2][64][XST]   67.6 KB
    float* wsm = xs + 2 * 64 * XST;        // [NWn]

    const int tid = threadIdx.x;
    const int u0  = blockIdx.x * UPC;
    const unsigned xs_u32 = (unsigned)__cvta_generic_to_shared(xs);

    // Kick off x prefetch for tiles 0 and 1 immediately (xs disjoint from ws).
    load_x_tile(x, xs_u32, 0, tid);
    load_x_tile(x, xs_u32 + 64 * XST * 4, 1, tid);

    // ---- Phase 1: build W rows in smem ----
    if (tid < NWn) wsm[tid] = w[tid];
    const float4 z4 = make_float4(0.f, 0.f, 0.f, 0.f);
    #pragma unroll
    for (int i = 0; i < 16; i++) ((float4*)ws)[i * 256 + tid] = z4;  // zero 64KB
    __syncthreads();

    const int NWL = NWn * L;
    #pragma unroll
    for (int uu = 0; uu < UPC; uu++) {
        const int* ip   = indices + (long)(u0 + uu) * NWL;
        float*     wrow = ws + uu * Dd;
        for (int e = tid; e < NWL; e += 256) {
            int idx    = __ldg(ip + e);
            unsigned k = (unsigned)(((unsigned long long)e * magicL) >> 32);  // e / L
            unsigned p = (unsigned)(idx - 1);       // idx==0 padding -> filtered
            if (p < (unsigned)Dd) wrow[p] = wsm[k];
        }
    }
    __syncthreads();   // ws ready for all warps

    // ---- Phase 2: pipelined GEMM ----
    const int b = tid & 63;    // batch row
    const int z = tid >> 6;    // k-segment (32 k's per tile)

    unsigned long long acc[UPC];
    #pragma unroll
    for (int j = 0; j < UPC; j++) acc[j] = 0ULL;    // (0.0f, 0.0f)

    for (int t = 0; t < NT; t++) {
        if (t == NT - 1) cp_wait<0>(); else cp_wait<1>();
        __syncthreads();

        const float* xb = xs + (t & 1) * 64 * XST + b * XST + z * 32;
        const float* wb = ws + t * BKt + z * 32;

        #pragma unroll
        for (int c = 0; c < 32; c += 4) {
            ulonglong2 xv = *(const ulonglong2*)(xb + c);     // k..k+3 of x row
            #pragma unroll
            for (int j = 0; j < UPC; j++) {
                ulonglong2 wv = *(const ulonglong2*)(wb + j * Dd + c);  // broadcast
                fma2(acc[j], xv.x, wv.x);
                fma2(acc[j], xv.y, wv.y);
            }
        }
        __syncthreads();
        if (t + 2 < NT) load_x_tile(x, xs_u32 + (t & 1) * 64 * XST * 4, t + 2, tid);
    }

    // ---- Cross-z reduction (overlay ws region) + bias + store ----
    float part[UPC];
    #pragma unroll
    for (int j = 0; j < UPC; j++) {
        unsigned long long v = acc[j];
        part[j] = __uint_as_float((unsigned)(v & 0xffffffffu)) +
                  __uint_as_float((unsigned)(v >> 32));
    }
    float* red = ws;   // safe: last __syncthreads in loop ordered all ws reads
    #pragma unroll
    for (int j = 0; j < UPC; j += 2)
        *(float2*)(red + (z * 64 + b) * UPC + j) = make_float2(part[j], part[j + 1]);
    __syncthreads();

    // 512 outputs per CTA; each thread sums 4 z-partials for one float2.
    const int b2 = tid >> 2;
    const int jp = (tid & 3) * 2;
    float2 s = make_float2(0.f, 0.f);
    #pragma unroll
    for (int zz = 0; zz < 4; zz++) {
        float2 v = *(const float2*)(red + (zz * 64 + b2) * UPC + jp);
        s.x += v.x; s.y += v.y;
    }
    s.x += __ldg(bias + u0 + jp);
    s.y += __ldg(bias + u0 + jp + 1);
    *(float2*)(out + (long)b2 * UNITSn + u0 + jp) = s;
}

// ---------------------------------------------------------------------------
extern "C" void kernel_launch(void* const* d_in, const int* in_sizes, int n_in,
                              void* d_out, int out_size) {
    const float* x       = (const float*)d_in[0];
    const float* w       = (const float*)d_in[1];
    const float* bias    = (const float*)d_in[2];
    const int*   indices = (const int*)d_in[3];
    float*       out     = (float*)d_out;

    const int L = in_sizes[3] / (UNITSn * NWn);
    const unsigned magicL =
        (unsigned)((0x100000000ULL + (unsigned long long)L - 1) / (unsigned long long)L);

    const int smem_bytes = (UPC * Dd + 2 * 64 * XST + NWn) * (int)sizeof(float); // ~133.6 KB
    cudaFuncSetAttribute(fused_kernel, cudaFuncAttributeMaxDynamicSharedMemorySize,
                         smem_bytes);

    fused_kernel<<<NCTA, 256, smem_bytes>>>(x, w, bias, indices, out, L, magicL);
}

// round 4
// speedup vs baseline: 1.4435x; 1.4435x over previous
#include <cuda_runtime.h>

// Problem constants: B=64, D=2048, UNITS=1024, NW=64
#define Bsz    64
#define Dd     2048
#define UNITSn 1024
#define NWn    64

#define UPC  8                 // units per CTA
#define NCTA (UNITSn / UPC)    // 128 CTAs
#define BKt  128               // k-tile width
#define NT   (Dd / BKt)        // 16 tiles
#define XST  132               // xs row stride (floats): 16B-aligned, conflict-free

__device__ __forceinline__ void fma2(unsigned long long& d,
                                     unsigned long long a,
                                     unsigned long long b) {
    asm("fma.rn.f32x2 %0, %1, %2, %0;" : "+l"(d) : "l"(a), "l"(b));
}
__device__ __forceinline__ void cp16(unsigned s, const void* g) {
    asm volatile("cp.async.cg.shared.global [%0], [%1], 16;" :: "r"(s), "l"(g));
}
__device__ __forceinline__ void cp_commit() {
    asm volatile("cp.async.commit_group;");
}
template <int N> __device__ __forceinline__ void cp_wait() {
    asm volatile("cp.async.wait_group %0;" :: "n"(N));
}
__device__ __forceinline__ unsigned mdiv(unsigned e, unsigned magic) {
    return (unsigned)(((unsigned long long)e * magic) >> 32);
}

// Prefetch x tile t (64 x 128 fp32 = 32KB) into xs buffer via cp.async.
__device__ __forceinline__ void load_x_tile(const float* __restrict__ x,
                                            unsigned xs_buf_u32, int t, int tid) {
    const int k0 = t * BKt;
    #pragma unroll
    for (int i = 0; i < 8; i++) {
        int idx = i * 256 + tid;          // 0..2047 float4 slots
        int r   = idx >> 5;               // batch row 0..63
        int c   = (idx & 31) << 2;        // k offset 0,4,...,124
        cp16(xs_buf_u32 + (unsigned)((r * XST + c) * 4),
             x + (long)r * Dd + k0 + c);
    }
    cp_commit();
}

// ---------------------------------------------------------------------------
// Fused: build 8 W rows in smem from hashed indices (int4-vectorized, MLP=8),
// then GEMM vs x streamed through a 2-stage cp.async pipeline.
// Thread map (phase 2): lane = 2 batch rows {lane, lane+32}; warp = k-segment
// of 16 within each 128-wide tile; 8 units per thread -> 16 f32x2 accs.
// W smem reads are warp-uniform broadcasts (1 wavefront each).
// ---------------------------------------------------------------------------
__global__ __launch_bounds__(256, 1) void fused_kernel(const float* __restrict__ x,
                                                       const float* __restrict__ w,
                                                       const float* __restrict__ bias,
                                                       const int* __restrict__ indices,
                                                       float* __restrict__ out,
                                                       int L, unsigned magicL) {
    extern __shared__ float sm[];
    float* ws  = sm;                       // [UPC][Dd]      64 KB (reused as reduce buf)
    float* xs  = sm + UPC * Dd;            // [2][64][XST]   67.6 KB
    float* wsm = xs + 2 * 64 * XST;        // [NWn]

    const int tid = threadIdx.x;
    const int u0  = blockIdx.x * UPC;
    const unsigned xs_u32 = (unsigned)__cvta_generic_to_shared(xs);

    // Kick off x prefetch for tiles 0 and 1 immediately (xs disjoint from ws).
    load_x_tile(x, xs_u32, 0, tid);
    load_x_tile(x, xs_u32 + 64 * XST * 4, 1, tid);

    // ---- Phase 1: build W rows in smem (batched int4 loads, 8 in flight) ----
    if (tid < NWn) wsm[tid] = w[tid];
    const float4 z4 = make_float4(0.f, 0.f, 0.f, 0.f);
    #pragma unroll
    for (int i = 0; i < 16; i++) ((float4*)ws)[i * 256 + tid] = z4;  // zero 64KB
    __syncthreads();

    {
        const int NWL4 = 16 * L;                       // int4 count per unit
        const int4* ind4 = (const int4*)indices + (long)u0 * NWL4;
        for (int e4 = tid; e4 < NWL4; e4 += 256) {
            int4 v[UPC];
            #pragma unroll
            for (int uu = 0; uu < UPC; uu++)
                v[uu] = __ldg(ind4 + (long)uu * NWL4 + e4);
            const int e = e4 * 4;
            const unsigned k0 = mdiv(e,     magicL);
            const unsigned k1 = mdiv(e + 1, magicL);
            const unsigned k2 = mdiv(e + 2, magicL);
            const unsigned k3 = mdiv(e + 3, magicL);
            #pragma unroll
            for (int uu = 0; uu < UPC; uu++) {
                float* wrow = ws + uu * Dd;
                unsigned p;
                p = (unsigned)(v[uu].x - 1); if (p < (unsigned)Dd) wrow[p] = wsm[k0];
                p = (unsigned)(v[uu].y - 1); if (p < (unsigned)Dd) wrow[p] = wsm[k1];
                p = (unsigned)(v[uu].z - 1); if (p < (unsigned)Dd) wrow[p] = wsm[k2];
                p = (unsigned)(v[uu].w - 1); if (p < (unsigned)Dd) wrow[p] = wsm[k3];
            }
        }
    }
    __syncthreads();   // ws ready for all warps

    // ---- Phase 2: pipelined GEMM ----
    const int lane = tid & 31;    // batch rows lane and lane+32
    const int z    = tid >> 5;    // warp id = k-segment (16 k's per tile)

    unsigned long long acc[2][UPC];
    #pragma unroll
    for (int r = 0; r < 2; r++)
        #pragma unroll
        for (int j = 0; j < UPC; j++) acc[r][j] = 0ULL;   // (0.0f, 0.0f)

    for (int t = 0; t < NT; t++) {
        if (t == NT - 1) cp_wait<0>(); else cp_wait<1>();
        __syncthreads();

        const float* xb0 = xs + (t & 1) * 64 * XST + lane * XST + z * 16;
        const float* xb1 = xb0 + 32 * XST;
        const float* wb  = ws + t * BKt + z * 16;

        #pragma unroll
        for (int c = 0; c < 16; c += 4) {
            ulonglong2 xv0 = *(const ulonglong2*)(xb0 + c);   // k..k+3, row lane
            ulonglong2 xv1 = *(const ulonglong2*)(xb1 + c);   // k..k+3, row lane+32
            #pragma unroll
            for (int j = 0; j < UPC; j++) {
                ulonglong2 wv = *(const ulonglong2*)(wb + j * Dd + c);  // uniform
                fma2(acc[0][j], xv0.x, wv.x);
                fma2(acc[0][j], xv0.y, wv.y);
                fma2(acc[1][j], xv1.x, wv.x);
                fma2(acc[1][j], xv1.y, wv.y);
            }
        }
        __syncthreads();
        if (t + 2 < NT) load_x_tile(x, xs_u32 + (t & 1) * 64 * XST * 4, t + 2, tid);
    }

    // ---- Cross-z reduction (overlay ws region) + bias + store ----
    float* red = ws;   // safe: loop's last __syncthreads ordered all ws reads
    #pragma unroll
    for (int r = 0; r < 2; r++) {
        const int b = lane + 32 * r;
        #pragma unroll
        for (int j = 0; j < UPC; j += 2) {
            unsigned long long v0 = acc[r][j], v1 = acc[r][j + 1];
            float s0 = __uint_as_float((unsigned)(v0 & 0xffffffffu)) +
                       __uint_as_float((unsigned)(v0 >> 32));
            float s1 = __uint_as_float((unsigned)(v1 & 0xffffffffu)) +
                       __uint_as_float((unsigned)(v1 >> 32));
            *(float2*)(red + (z * 64 + b) * UPC + j) = make_float2(s0, s1);
        }
    }
    __syncthreads();

    // 512 outputs per CTA; each thread sums 8 z-partials for one float2.
    const int b2 = tid >> 2;
    const int jp = (tid & 3) * 2;
    float2 s = make_float2(0.f, 0.f);
    #pragma unroll
    for (int zz = 0; zz < 8; zz++) {
        float2 v = *(const float2*)(red + (zz * 64 + b2) * UPC + jp);
        s.x += v.x; s.y += v.y;
    }
    s.x += __ldg(bias + u0 + jp);
    s.y += __ldg(bias + u0 + jp + 1);
    *(float2*)(out + (long)b2 * UNITSn + u0 + jp) = s;
}

// ---------------------------------------------------------------------------
extern "C" void kernel_launch(void* const* d_in, const int* in_sizes, int n_in,
                              void* d_out, int out_size) {
    const float* x       = (const float*)d_in[0];
    const float* w       = (const float*)d_in[1];
    const float* bias    = (const float*)d_in[2];
    const int*   indices = (const int*)d_in[3];
    float*       out     = (float*)d_out;

    const int L = in_sizes[3] / (UNITSn * NWn);
    const unsigned magicL =
        (unsigned)((0x100000000ULL + (unsigned long long)L - 1) / (unsigned long long)L);

    const int smem_bytes = (UPC * Dd + 2 * 64 * XST + NWn) * (int)sizeof(float); // ~133.6 KB
    cudaFuncSetAttribute(fused_kernel, cudaFuncAttributeMaxDynamicSharedMemorySize,
                         smem_bytes);

    fused_kernel<<<NCTA, 256, smem_bytes>>>(x, w, bias, indices, out, L, magicL);
}